// round 9
// baseline (speedup 1.0000x reference)
#include <cuda_runtime.h>
#include <cuda_fp16.h>
#include <cstdint>

// ---------------------------------------------------------------------------
// out = relu(x @ W_ih^T + (h0@W_hh^T + b_ih + b_hh)) @ W_out + b_out
// fp16 mma.sync.m16n8k16 (fp32 accumulate), fused two-GEMM pipeline.
// R9: 4 slabs/warp (64 rows) -> weight-fragment LDS per row halves.
// B1 packed as uint4 j-pairs (j=2q,2q+1), B2 as uint4 t-pairs: half the
// LDS instructions for the same bytes. 4 warps/CTA, 3 CTAs/SM, cap 170 regs.
// ---------------------------------------------------------------------------

static constexpr int NIN      = 64;
static constexpr int NH       = 128;
static constexpr int NOUT     = 32;
static constexpr int TILE_M   = 256;           // 4 warps x 64 rows
static constexpr int T_TOTAL  = 1048576;
static constexpr int NTILES   = T_TOTAL / TILE_M;   // 4096
static constexpr int GRID     = 456;           // 3 CTAs/SM x 152 SMs
static constexpr int KTHREADS = 128;           // 4 warps

// x staging: per-warp fp16 buffer, 64 rows x 36 words (fp16x2), 9216 B
static constexpr int XPITCH_W = 36;
static constexpr int XBUF_B   = 64 * XPITCH_W * 4;   // 9216

// ---- smem byte offsets ----
static constexpr int SM_CP  = 0;               // hidden drive pairs, 64 float2
static constexpr int SM_BO  = 512;             // 32 f32 b_out
static constexpr int SM_B1  = 1024;            // W_ih uint4 pack, 16 KB
static constexpr int SM_B2  = SM_B1 + 16384;   // W_out uint4 pack, 8 KB
static constexpr int SM_CT  = SM_B2 + 8192;    // 128 f32 raw hidden drive
static constexpr int SM_X   = SM_CT + 512;     // 4 x 9216 per-warp x buffers
static constexpr int SMEM_BYTES = SM_X + 4 * XBUF_B;   // 62592

__device__ __forceinline__ uint32_t packh2(float lo, float hi) {
    uint32_t r;
    asm("cvt.rn.f16x2.f32 %0, %1, %2;" : "=r"(r) : "f"(hi), "f"(lo));
    return r;
}

__device__ __forceinline__ void mma_fp16(float* d,
                                         const uint32_t* a,
                                         uint32_t b0, uint32_t b1) {
    asm volatile(
        "mma.sync.aligned.m16n8k16.row.col.f32.f16.f16.f32 "
        "{%0,%1,%2,%3}, {%4,%5,%6,%7}, {%8,%9}, {%0,%1,%2,%3};"
        : "+f"(d[0]), "+f"(d[1]), "+f"(d[2]), "+f"(d[3])
        : "r"(a[0]), "r"(a[1]), "r"(a[2]), "r"(a[3]), "r"(b0), "r"(b1));
}

// ---------------------------------------------------------------------------
__global__ void __launch_bounds__(KTHREADS, 3)
rnn_model_kernel(const float* __restrict__ x,
                 const float* __restrict__ W_ih,
                 const float* __restrict__ W_hh,
                 const float* __restrict__ b_ih,
                 const float* __restrict__ b_hh,
                 const float* __restrict__ W_out,
                 const float* __restrict__ b_out,
                 const float* __restrict__ h0,
                 float* __restrict__ out)
{
    extern __shared__ char smem[];
    const int tid  = threadIdx.x;
    const int wid  = tid >> 5;
    const int lane = tid & 31;
    const int g    = lane >> 2;   // row within fragment
    const int o    = lane & 3;    // col pair within fragment

    uint4*  B1p = reinterpret_cast<uint4*>(smem + SM_B1);  // [(c*8+q)*32+lane]
    uint4*  B2p = reinterpret_cast<uint4*>(smem + SM_B2);  // [(q*2+tp)*32+lane]
    float2* CP  = reinterpret_cast<float2*>(smem + SM_CP);
    float*  CT  = reinterpret_cast<float*>(smem + SM_CT);
    float2* BO  = reinterpret_cast<float2*>(smem + SM_BO);
    uint32_t* XW = reinterpret_cast<uint32_t*>(smem + SM_X + wid * XBUF_B);

    // ---- one-time fragment packs ----
    // B1 j-pair pack: entry (c,q,lane): halves for j0=2q (x,y) and j1=2q+1 (z,w)
    //   x = {W[16q+g'][16c+2o], +1}, y = {..+8, +9}; z,w same at row 16q+8+g'
    for (int e = tid; e < 4 * 8 * 32; e += KTHREADS) {
        int c = e >> 8, q = (e >> 5) & 7, l = e & 31;
        int r0  = 16 * q + (l >> 2);
        int col = 16 * c + 2 * (l & 3);
        const float* p0 = W_ih + r0 * NIN + col;
        const float* p1 = p0 + 8 * NIN;
        uint4 v;
        v.x = packh2(p0[0], p0[1]); v.y = packh2(p0[8], p0[9]);
        v.z = packh2(p1[0], p1[1]); v.w = packh2(p1[8], p1[9]);
        B1p[e] = v;
    }
    // B2 t-pair pack: entry (q,tp,lane): t0=2tp (x,y), t1=2tp+1 (z,w)
    //   x = {W_out[16q+2o][8t+g'], W_out[16q+2o+1][8t+g']}, y = rows +8,+9
    for (int e = tid; e < 8 * 2 * 32; e += KTHREADS) {
        int q = e >> 6, tp = (e >> 5) & 1, l = e & 31;
        int r  = 16 * q + 2 * (l & 3);
        int c0 = 16 * tp + (l >> 2);
        const float* p = W_out + r * NOUT;
        uint4 v;
        v.x = packh2(p[c0],            p[NOUT + c0]);
        v.y = packh2(p[8 * NOUT + c0], p[9 * NOUT + c0]);
        v.z = packh2(p[c0 + 8],            p[NOUT + c0 + 8]);
        v.w = packh2(p[8 * NOUT + c0 + 8], p[9 * NOUT + c0 + 8]);
        B2p[e] = v;
    }
    {   // hidden drive c = h0 @ W_hh^T + b_ih + b_hh (fp32 exact)
        float c = b_ih[tid] + b_hh[tid];
        const float4* hh = reinterpret_cast<const float4*>(W_hh + (size_t)tid * NH);
        const float4* h4 = reinterpret_cast<const float4*>(h0);
        #pragma unroll 8
        for (int q = 0; q < NH / 4; q++) {
            float4 w = hh[q], h = h4[q];
            c += w.x * h.x + w.y * h.y + w.z * h.z + w.w * h.w;
        }
        CT[tid] = c;
    }
    if (tid < NOUT / 2) BO[tid] = make_float2(b_out[2 * tid], b_out[2 * tid + 1]);
    __syncthreads();
    if (tid < 64) {
        int j = tid >> 2, oo = tid & 3;
        CP[tid] = make_float2(CT[8 * j + 2 * oo], CT[8 * j + 2 * oo + 1]);
    }
    __syncthreads();

    for (int tile = blockIdx.x; tile < NTILES; tile += GRID) {
        // ---- stage 64 x-rows: coalesced LDG.128 -> fp16 smem ----
        const float4* xt = reinterpret_cast<const float4*>(
            x + ((size_t)tile * TILE_M + wid * 64) * NIN);
        #pragma unroll
        for (int i = 0; i < 32; i++) {
            int f = i * 32 + lane;            // float4 index, 0..1023
            float4 v = xt[f];
            int row = f >> 4;
            int w   = (f & 15) * 2;
            *reinterpret_cast<uint2*>(XW + row * XPITCH_W + w) =
                make_uint2(packh2(v.x, v.y), packh2(v.z, v.w));
        }
        __syncwarp();

        // ---- A fragments: conflict-free LDS.32 (bank = 4g+o), 4 slabs ----
        uint32_t a[4][4][4];
        #pragma unroll
        for (int s = 0; s < 4; s++) {
            const uint32_t* r0 = XW + (s * 16 + g) * XPITCH_W + o;
            const uint32_t* r1 = r0 + 8 * XPITCH_W;
            #pragma unroll
            for (int c = 0; c < 4; c++) {
                a[s][c][0] = r0[8 * c];
                a[s][c][1] = r1[8 * c];
                a[s][c][2] = r0[8 * c + 4];
                a[s][c][3] = r1[8 * c + 4];
            }
        }
        __syncwarp();

        // ---- fused GEMM1 -> relu/pack -> GEMM2, 4 slabs ----
        float e[4][4][4];
        #pragma unroll
        for (int s = 0; s < 4; s++)
            #pragma unroll
            for (int t = 0; t < 4; t++)
                #pragma unroll
                for (int r = 0; r < 4; r++) e[s][t][r] = 0.f;

        #pragma unroll
        for (int q = 0; q < 8; q++) {
            uint4 bb0 = B1p[(0 * 8 + q) * 32 + lane];
            uint4 bb1 = B1p[(1 * 8 + q) * 32 + lane];
            uint4 bb2 = B1p[(2 * 8 + q) * 32 + lane];
            uint4 bb3 = B1p[(3 * 8 + q) * 32 + lane];
            uint4 b2a = B2p[(q * 2 + 0) * 32 + lane];
            uint4 b2b = B2p[(q * 2 + 1) * 32 + lane];
            float2 cd0 = CP[(2 * q + 0) * 4 + o];
            float2 cd1 = CP[(2 * q + 1) * 4 + o];

            #pragma unroll
            for (int p = 0; p < 2; p++) {       // slab pairs (0,1) and (2,3)
                const int s0 = 2 * p, s1 = 2 * p + 1;
                uint32_t h0[4], h1[4];
                // jj = 0 (j = 2q)
                {
                    float d0[4] = {0,0,0,0}, d1[4] = {0,0,0,0};
                    mma_fp16(d0, a[s0][0], bb0.x, bb0.y);
                    mma_fp16(d1, a[s1][0], bb0.x, bb0.y);
                    mma_fp16(d0, a[s0][1], bb1.x, bb1.y);
                    mma_fp16(d1, a[s1][1], bb1.x, bb1.y);
                    mma_fp16(d0, a[s0][2], bb2.x, bb2.y);
                    mma_fp16(d1, a[s1][2], bb2.x, bb2.y);
                    mma_fp16(d0, a[s0][3], bb3.x, bb3.y);
                    mma_fp16(d1, a[s1][3], bb3.x, bb3.y);
                    h0[0] = packh2(fmaxf(d0[0] + cd0.x, 0.f), fmaxf(d0[1] + cd0.y, 0.f));
                    h0[1] = packh2(fmaxf(d0[2] + cd0.x, 0.f), fmaxf(d0[3] + cd0.y, 0.f));
                    h1[0] = packh2(fmaxf(d1[0] + cd0.x, 0.f), fmaxf(d1[1] + cd0.y, 0.f));
                    h1[1] = packh2(fmaxf(d1[2] + cd0.x, 0.f), fmaxf(d1[3] + cd0.y, 0.f));
                }
                // jj = 1 (j = 2q+1)
                {
                    float d0[4] = {0,0,0,0}, d1[4] = {0,0,0,0};
                    mma_fp16(d0, a[s0][0], bb0.z, bb0.w);
                    mma_fp16(d1, a[s1][0], bb0.z, bb0.w);
                    mma_fp16(d0, a[s0][1], bb1.z, bb1.w);
                    mma_fp16(d1, a[s1][1], bb1.z, bb1.w);
                    mma_fp16(d0, a[s0][2], bb2.z, bb2.w);
                    mma_fp16(d1, a[s1][2], bb2.z, bb2.w);
                    mma_fp16(d0, a[s0][3], bb3.z, bb3.w);
                    mma_fp16(d1, a[s1][3], bb3.z, bb3.w);
                    h0[2] = packh2(fmaxf(d0[0] + cd1.x, 0.f), fmaxf(d0[1] + cd1.y, 0.f));
                    h0[3] = packh2(fmaxf(d0[2] + cd1.x, 0.f), fmaxf(d0[3] + cd1.y, 0.f));
                    h1[2] = packh2(fmaxf(d1[0] + cd1.x, 0.f), fmaxf(d1[1] + cd1.y, 0.f));
                    h1[3] = packh2(fmaxf(d1[2] + cd1.x, 0.f), fmaxf(d1[3] + cd1.y, 0.f));
                }
                // GEMM2 accumulate (B2 frags shared by both slab pairs)
                mma_fp16(e[s0][0], h0, b2a.x, b2a.y);
                mma_fp16(e[s0][1], h0, b2a.z, b2a.w);
                mma_fp16(e[s0][2], h0, b2b.x, b2b.y);
                mma_fp16(e[s0][3], h0, b2b.z, b2b.w);
                mma_fp16(e[s1][0], h1, b2a.x, b2a.y);
                mma_fp16(e[s1][1], h1, b2a.z, b2a.w);
                mma_fp16(e[s1][2], h1, b2b.x, b2b.y);
                mma_fp16(e[s1][3], h1, b2b.z, b2b.w);
            }
        }

        // ---- epilogue: + b_out, coalesced float2 stores, 4 slabs ----
        #pragma unroll
        for (int s = 0; s < 4; s++) {
            const size_t rbase = (size_t)tile * TILE_M + wid * 64 + s * 16 + g;
            float* o0 = out + rbase * NOUT + 2 * o;
            float* o1 = o0 + 8 * NOUT;
            #pragma unroll
            for (int t = 0; t < 4; t++) {
                float2 bo = BO[t * 4 + o];
                *reinterpret_cast<float2*>(o0 + 8 * t) =
                    make_float2(e[s][t][0] + bo.x, e[s][t][1] + bo.y);
                *reinterpret_cast<float2*>(o1 + 8 * t) =
                    make_float2(e[s][t][2] + bo.x, e[s][t][3] + bo.y);
            }
        }
        __syncwarp();   // order next tile's staging after this tile's reads
    }
}

// ---------------------------------------------------------------------------
extern "C" void kernel_launch(void* const* d_in, const int* in_sizes, int n_in,
                              void* d_out, int out_size) {
    const float* x     = (const float*)d_in[0];
    const float* W_ih  = (const float*)d_in[1];
    const float* W_hh  = (const float*)d_in[2];
    const float* b_ih  = (const float*)d_in[3];
    const float* b_hh  = (const float*)d_in[4];
    const float* W_out = (const float*)d_in[5];
    const float* b_out = (const float*)d_in[6];
    const float* h0    = (const float*)d_in[7];
    float* out = (float*)d_out;

    cudaFuncSetAttribute(rnn_model_kernel,
                         cudaFuncAttributeMaxDynamicSharedMemorySize, SMEM_BYTES);
    rnn_model_kernel<<<GRID, KTHREADS, SMEM_BYTES>>>(
        x, W_ih, W_hh, b_ih, b_hh, W_out, b_out, h0, out);
}

// round 10
// speedup vs baseline: 1.1166x; 1.1166x over previous
#include <cuda_runtime.h>
#include <cuda_fp16.h>
#include <cstdint>

// ---------------------------------------------------------------------------
// out = relu(x @ W_ih^T + (h0@W_hh^T + b_ih + b_hh)) @ W_out + b_out
// fp16 mma.sync.m16n8k16 (fp32 accumulate), fused two-GEMM pipeline.
// R10: back to 2 slabs/warp (R8 anchor) but 6 warps/CTA x 3 CTAs/SM
// = 18 warps/SM (vs 16). Warps grid-stride over global 32-row units.
// R9's uint4 j-pair / t-pair weight packs kept (half the LDS instructions).
// ---------------------------------------------------------------------------

static constexpr int NIN      = 64;
static constexpr int NH       = 128;
static constexpr int NOUT     = 32;
static constexpr int T_TOTAL  = 1048576;
static constexpr int UNITS    = T_TOTAL / 32;      // 32768 32-row units
static constexpr int GRID     = 456;               // 3 CTAs/SM x 152 SMs
static constexpr int KTHREADS = 192;               // 6 warps
static constexpr int NWARPS   = GRID * 6;          // 2736

// x staging: per-warp fp16 buffer, 32 rows x 36 words (fp16x2), 4608 B
static constexpr int XPITCH_W = 36;
static constexpr int XBUF_B   = 32 * XPITCH_W * 4; // 4608

// ---- smem byte offsets ----
static constexpr int SM_CP  = 0;                   // hidden drive pairs
static constexpr int SM_BO  = 512;                 // 32 f32 b_out
static constexpr int SM_B1  = 1024;                // W_ih uint4 pack, 16 KB
static constexpr int SM_B2  = SM_B1 + 16384;       // W_out uint4 pack, 8 KB
static constexpr int SM_CT  = SM_B2 + 8192;        // 128 f32 raw drive (temp)
static constexpr int SM_X   = SM_CT + 512;         // 6 x 4608 per-warp x bufs
static constexpr int SMEM_BYTES = SM_X + 6 * XBUF_B;   // 53760

__device__ __forceinline__ uint32_t packh2(float lo, float hi) {
    uint32_t r;
    asm("cvt.rn.f16x2.f32 %0, %1, %2;" : "=r"(r) : "f"(hi), "f"(lo));
    return r;
}

__device__ __forceinline__ void mma_fp16(float* d,
                                         const uint32_t* a,
                                         uint32_t b0, uint32_t b1) {
    asm volatile(
        "mma.sync.aligned.m16n8k16.row.col.f32.f16.f16.f32 "
        "{%0,%1,%2,%3}, {%4,%5,%6,%7}, {%8,%9}, {%0,%1,%2,%3};"
        : "+f"(d[0]), "+f"(d[1]), "+f"(d[2]), "+f"(d[3])
        : "r"(a[0]), "r"(a[1]), "r"(a[2]), "r"(a[3]), "r"(b0), "r"(b1));
}

// ---------------------------------------------------------------------------
__global__ void __launch_bounds__(KTHREADS, 3)
rnn_model_kernel(const float* __restrict__ x,
                 const float* __restrict__ W_ih,
                 const float* __restrict__ W_hh,
                 const float* __restrict__ b_ih,
                 const float* __restrict__ b_hh,
                 const float* __restrict__ W_out,
                 const float* __restrict__ b_out,
                 const float* __restrict__ h0,
                 float* __restrict__ out)
{
    extern __shared__ char smem[];
    const int tid  = threadIdx.x;
    const int wid  = tid >> 5;
    const int lane = tid & 31;
    const int g    = lane >> 2;   // row within fragment
    const int o    = lane & 3;    // col pair within fragment

    uint4*  B1p = reinterpret_cast<uint4*>(smem + SM_B1);  // [(c*8+q)*32+lane]
    uint4*  B2p = reinterpret_cast<uint4*>(smem + SM_B2);  // [(q*2+tp)*32+lane]
    float2* CP  = reinterpret_cast<float2*>(smem + SM_CP);
    float*  CT  = reinterpret_cast<float*>(smem + SM_CT);
    float2* BO  = reinterpret_cast<float2*>(smem + SM_BO);
    uint32_t* XW = reinterpret_cast<uint32_t*>(smem + SM_X + wid * XBUF_B);

    // ---- one-time fragment packs (validated in R9) ----
    // B1 j-pair pack: (c,q,lane): x,y = j0=2q frag halves; z,w = j1=2q+1
    for (int e = tid; e < 4 * 8 * 32; e += KTHREADS) {
        int c = e >> 8, q = (e >> 5) & 7, l = e & 31;
        int r0  = 16 * q + (l >> 2);
        int col = 16 * c + 2 * (l & 3);
        const float* p0 = W_ih + r0 * NIN + col;
        const float* p1 = p0 + 8 * NIN;
        uint4 v;
        v.x = packh2(p0[0], p0[1]); v.y = packh2(p0[8], p0[9]);
        v.z = packh2(p1[0], p1[1]); v.w = packh2(p1[8], p1[9]);
        B1p[e] = v;
    }
    // B2 t-pair pack: (q,tp,lane): x,y = t0=2tp; z,w = t1=2tp+1
    for (int e = tid; e < 8 * 2 * 32; e += KTHREADS) {
        int q = e >> 6, tp = (e >> 5) & 1, l = e & 31;
        int r  = 16 * q + 2 * (l & 3);
        int c0 = 16 * tp + (l >> 2);
        const float* p = W_out + r * NOUT;
        uint4 v;
        v.x = packh2(p[c0],            p[NOUT + c0]);
        v.y = packh2(p[8 * NOUT + c0], p[9 * NOUT + c0]);
        v.z = packh2(p[c0 + 8],            p[NOUT + c0 + 8]);
        v.w = packh2(p[8 * NOUT + c0 + 8], p[9 * NOUT + c0 + 8]);
        B2p[e] = v;
    }
    if (tid < NH) {   // hidden drive c = h0 @ W_hh^T + b_ih + b_hh (fp32)
        float c = b_ih[tid] + b_hh[tid];
        const float4* hh = reinterpret_cast<const float4*>(W_hh + (size_t)tid * NH);
        const float4* h4 = reinterpret_cast<const float4*>(h0);
        #pragma unroll 8
        for (int q = 0; q < NH / 4; q++) {
            float4 w = hh[q], h = h4[q];
            c += w.x * h.x + w.y * h.y + w.z * h.z + w.w * h.w;
        }
        CT[tid] = c;
    }
    if (tid < NOUT / 2) BO[tid] = make_float2(b_out[2 * tid], b_out[2 * tid + 1]);
    __syncthreads();
    if (tid < 64) {
        int j = tid >> 2, oo = tid & 3;
        CP[tid] = make_float2(CT[8 * j + 2 * oo], CT[8 * j + 2 * oo + 1]);
    }
    __syncthreads();

    const int gw = blockIdx.x * 6 + wid;   // global warp id

    for (int u = gw; u < UNITS; u += NWARPS) {
        // ---- stage this unit's 32 x-rows: coalesced LDG.128 -> fp16 smem ----
        const float4* xt = reinterpret_cast<const float4*>(
            x + (size_t)u * 32 * NIN);
        #pragma unroll
        for (int i = 0; i < 16; i++) {
            int f = i * 32 + lane;            // float4 index, 0..511
            float4 v = xt[f];
            int row = f >> 4;
            int w   = (f & 15) * 2;
            *reinterpret_cast<uint2*>(XW + row * XPITCH_W + w) =
                make_uint2(packh2(v.x, v.y), packh2(v.z, v.w));
        }
        __syncwarp();

        // ---- A fragments: conflict-free LDS.32 (bank = 4g+o), 2 slabs ----
        uint32_t a[2][4][4];
        #pragma unroll
        for (int s = 0; s < 2; s++) {
            const uint32_t* r0 = XW + (s * 16 + g) * XPITCH_W + o;
            const uint32_t* r1 = r0 + 8 * XPITCH_W;
            #pragma unroll
            for (int c = 0; c < 4; c++) {
                a[s][c][0] = r0[8 * c];
                a[s][c][1] = r1[8 * c];
                a[s][c][2] = r0[8 * c + 4];
                a[s][c][3] = r1[8 * c + 4];
            }
        }
        __syncwarp();

        // ---- fused GEMM1 -> relu/pack -> GEMM2, 2 slabs ----
        float e[2][4][4];
        #pragma unroll
        for (int s = 0; s < 2; s++)
            #pragma unroll
            for (int t = 0; t < 4; t++)
                #pragma unroll
                for (int r = 0; r < 4; r++) e[s][t][r] = 0.f;

        #pragma unroll
        for (int q = 0; q < 8; q++) {
            uint4 bb0 = B1p[(0 * 8 + q) * 32 + lane];
            uint4 bb1 = B1p[(1 * 8 + q) * 32 + lane];
            uint4 bb2 = B1p[(2 * 8 + q) * 32 + lane];
            uint4 bb3 = B1p[(3 * 8 + q) * 32 + lane];
            uint4 b2a = B2p[(q * 2 + 0) * 32 + lane];
            uint4 b2b = B2p[(q * 2 + 1) * 32 + lane];
            float2 cd0 = CP[(2 * q + 0) * 4 + o];
            float2 cd1 = CP[(2 * q + 1) * 4 + o];

            uint32_t h0[4], h1[4];
            // jj = 0 (j = 2q)
            {
                float d0[4] = {0,0,0,0}, d1[4] = {0,0,0,0};
                mma_fp16(d0, a[0][0], bb0.x, bb0.y);
                mma_fp16(d1, a[1][0], bb0.x, bb0.y);
                mma_fp16(d0, a[0][1], bb1.x, bb1.y);
                mma_fp16(d1, a[1][1], bb1.x, bb1.y);
                mma_fp16(d0, a[0][2], bb2.x, bb2.y);
                mma_fp16(d1, a[1][2], bb2.x, bb2.y);
                mma_fp16(d0, a[0][3], bb3.x, bb3.y);
                mma_fp16(d1, a[1][3], bb3.x, bb3.y);
                h0[0] = packh2(fmaxf(d0[0] + cd0.x, 0.f), fmaxf(d0[1] + cd0.y, 0.f));
                h0[1] = packh2(fmaxf(d0[2] + cd0.x, 0.f), fmaxf(d0[3] + cd0.y, 0.f));
                h1[0] = packh2(fmaxf(d1[0] + cd0.x, 0.f), fmaxf(d1[1] + cd0.y, 0.f));
                h1[1] = packh2(fmaxf(d1[2] + cd0.x, 0.f), fmaxf(d1[3] + cd0.y, 0.f));
            }
            // jj = 1 (j = 2q+1)
            {
                float d0[4] = {0,0,0,0}, d1[4] = {0,0,0,0};
                mma_fp16(d0, a[0][0], bb0.z, bb0.w);
                mma_fp16(d1, a[1][0], bb0.z, bb0.w);
                mma_fp16(d0, a[0][1], bb1.z, bb1.w);
                mma_fp16(d1, a[1][1], bb1.z, bb1.w);
                mma_fp16(d0, a[0][2], bb2.z, bb2.w);
                mma_fp16(d1, a[1][2], bb2.z, bb2.w);
                mma_fp16(d0, a[0][3], bb3.z, bb3.w);
                mma_fp16(d1, a[1][3], bb3.z, bb3.w);
                h0[2] = packh2(fmaxf(d0[0] + cd1.x, 0.f), fmaxf(d0[1] + cd1.y, 0.f));
                h0[3] = packh2(fmaxf(d0[2] + cd1.x, 0.f), fmaxf(d0[3] + cd1.y, 0.f));
                h1[2] = packh2(fmaxf(d1[0] + cd1.x, 0.f), fmaxf(d1[1] + cd1.y, 0.f));
                h1[3] = packh2(fmaxf(d1[2] + cd1.x, 0.f), fmaxf(d1[3] + cd1.y, 0.f));
            }
            // GEMM2 accumulate
            mma_fp16(e[0][0], h0, b2a.x, b2a.y);
            mma_fp16(e[0][1], h0, b2a.z, b2a.w);
            mma_fp16(e[0][2], h0, b2b.x, b2b.y);
            mma_fp16(e[0][3], h0, b2b.z, b2b.w);
            mma_fp16(e[1][0], h1, b2a.x, b2a.y);
            mma_fp16(e[1][1], h1, b2a.z, b2a.w);
            mma_fp16(e[1][2], h1, b2b.x, b2b.y);
            mma_fp16(e[1][3], h1, b2b.z, b2b.w);
        }

        // ---- epilogue: + b_out, coalesced float2 stores, 2 slabs ----
        #pragma unroll
        for (int s = 0; s < 2; s++) {
            const size_t rbase = (size_t)u * 32 + s * 16 + g;
            float* o0 = out + rbase * NOUT + 2 * o;
            float* o1 = o0 + 8 * NOUT;
            #pragma unroll
            for (int t = 0; t < 4; t++) {
                float2 bo = BO[t * 4 + o];
                *reinterpret_cast<float2*>(o0 + 8 * t) =
                    make_float2(e[s][t][0] + bo.x, e[s][t][1] + bo.y);
                *reinterpret_cast<float2*>(o1 + 8 * t) =
                    make_float2(e[s][t][2] + bo.x, e[s][t][3] + bo.y);
            }
        }
        __syncwarp();   // order next unit's staging after this unit's reads
    }
}

// ---------------------------------------------------------------------------
extern "C" void kernel_launch(void* const* d_in, const int* in_sizes, int n_in,
                              void* d_out, int out_size) {
    const float* x     = (const float*)d_in[0];
    const float* W_ih  = (const float*)d_in[1];
    const float* W_hh  = (const float*)d_in[2];
    const float* b_ih  = (const float*)d_in[3];
    const float* b_hh  = (const float*)d_in[4];
    const float* W_out = (const float*)d_in[5];
    const float* b_out = (const float*)d_in[6];
    const float* h0    = (const float*)d_in[7];
    float* out = (float*)d_out;

    cudaFuncSetAttribute(rnn_model_kernel,
                         cudaFuncAttributeMaxDynamicSharedMemorySize, SMEM_BYTES);
    rnn_model_kernel<<<GRID, KTHREADS, SMEM_BYTES>>>(
        x, W_ih, W_hh, b_ih, b_hh, W_out, b_out, h0, out);
}